// round 12
// baseline (speedup 1.0000x reference)
#include <cuda_runtime.h>

// Problem constants (fixed by the dataset shapes)
#define B_   32
#define NL_  13
#define L_   1024
#define D_   768
#define LCHUNKS_ 32
#define LCHUNK_  (L_ / LCHUNKS_)   // 32 rows per block
#define NT_  (D_ / 4)              // 192 threads

// Scratch (no allocation allowed).
__device__ float g_w[B_ * L_];
__device__ int   g_flag[B_];       // zero-initialized; stays 1 after first run
                                   // (benign: writers rewrite identical g_w)

// ---------------------------------------------------------------------------
// Kernel A: zero the poisoned output (98 KB). PDL producer: the fused
// kernel's epilogue reductions are gated on this via griddepcontrol.
// ---------------------------------------------------------------------------
__global__ void zero_out_kernel(float* __restrict__ out)
{
    out[blockIdx.x * D_ + threadIdx.x] = 0.0f;
    asm volatile("griddepcontrol.launch_dependents;");
}

// ---------------------------------------------------------------------------
// Fused kernel: grid (32 chunks, 32 batches) = 1024 blocks = ONE wave
// (capacity 8 blocks/SM x 148 SM = 1184 >= 1024 -> all co-resident, so the
// intra-grid flag handshake cannot deadlock). 192 threads/block.
//
// lc==0 blocks ("writers", one per batch): compute batch b's run-length
//   weights (vq -> smem, boundary flags, block-reduced num_runs, O(1) local
//   walks since adjacent vq pairs collide with prob ~1/320^2), store g_w,
//   threadfence, release g_flag[b]. Then run their own pool chunk.
// Other blocks ("readers"): prefetch their first 8 feature rows FIRST (the
//   24 MB of in-flight loads hides the writers' ~1us weight phase), then
//   acquire-spin on g_flag[b], then stream the remaining 24 rows with the
//   proven 8-deep batched __ldcs LDG.128 schedule.
// Epilogue: griddepcontrol.wait (zero kernel done) + one red.global.v4.f32.
//
// Integer inputs are read through an int32 view with runtime-detected element
// stride (JAX silently downcasts int64->int32 without x64). lengths are in
// [512,1024] (never 0), so word[1]==0  <=>  little-endian int64 layout.
// vq values < 320 < 2^31, so low words fully determine equality either way.
// ---------------------------------------------------------------------------
__global__ void __launch_bounds__(NT_, 8)
vq_fused_kernel(const float* __restrict__ feat,
                const int*   __restrict__ len32,
                const int*   __restrict__ vq32,
                float*       __restrict__ out)
{
    const int b    = blockIdx.y;
    const int lc   = blockIdx.x;
    const int t    = threadIdx.x;   // 0..191
    const int lane = t & 31;
    const int warp = t >> 5;

    __shared__ int           s_v0[L_];
    __shared__ int           s_v1[L_];
    __shared__ unsigned char s_bnd[L_];
    __shared__ int           s_red[NT_ / 32];
    __shared__ int           s_nr;

    // dtype detection (uniform)
    const int stride = (len32[1] == 0) ? 2 : 1;
    const int len    = len32[b * stride];

    const int l0 = lc * LCHUNK_;
    if (l0 >= len) return;          // whole chunk zero-weight (uniform exit)

    const float4* __restrict__ fb = (const float4*)
        (feat + ((size_t)b * NL_ + (NL_ - 1)) * (size_t)(L_ * D_));
    const float4* __restrict__ wb4 = (const float4*)(g_w + b * L_);
    float* ob = out + b * D_ + t * 4;

    float4 f[8];

    if (lc == 0) {
        // ---------------- writer: weights for batch b ----------------
        const int vbase = b * L_ * 2;
        #pragma unroll 2
        for (int idx = t; idx < L_; idx += NT_) {
            s_v0[idx] = vq32[(vbase + 2 * idx + 0) * stride];
            s_v1[idx] = vq32[(vbase + 2 * idx + 1) * stride];
        }
        __syncthreads();

        int cnt = 0;
        #pragma unroll 2
        for (int idx = t; idx < L_; idx += NT_) {
            bool bnd = (idx < len) &&
                       (idx == 0 || s_v0[idx] != s_v0[idx - 1]
                                 || s_v1[idx] != s_v1[idx - 1]);
            s_bnd[idx] = bnd ? 1 : 0;
            cnt += bnd ? 1 : 0;
        }
        #pragma unroll
        for (int off = 16; off > 0; off >>= 1)
            cnt += __shfl_down_sync(0xffffffffu, cnt, off);
        if (lane == 0) s_red[warp] = cnt;
        __syncthreads();
        if (t == 0) {
            int tot = 0;
            #pragma unroll
            for (int w = 0; w < NT_ / 32; ++w) tot += s_red[w];
            s_nr = tot;
        }
        __syncthreads();

        const float nr = (float)s_nr;
        #pragma unroll 2
        for (int idx = t; idx < L_; idx += NT_) {
            float wv = 0.0f;
            if (idx < len) {
                int s = idx;
                while (!s_bnd[s]) --s;               // expected 0 iterations
                int e = idx + 1;
                while (e < len && !s_bnd[e]) ++e;    // expected 0 iterations
                wv = 1.0f / (nr * (float)(e - s));
            }
            g_w[b * L_ + idx] = wv;
        }
        __threadfence();
        __syncthreads();
        if (t == 0)
            asm volatile("st.release.gpu.global.u32 [%0], %1;"
                         :: "l"(&g_flag[b]), "r"(1) : "memory");

        // prefetch own first 8 rows (after weight phase: lower reg pressure)
        #pragma unroll
        for (int k = 0; k < 8; ++k)
            f[k] = __ldcs(&fb[(size_t)(l0 + k) * NT_ + t]);
    } else {
        // ---------------- reader: prefetch, then wait ----------------
        #pragma unroll
        for (int k = 0; k < 8; ++k)
            f[k] = __ldcs(&fb[(size_t)(l0 + k) * NT_ + t]);

        if (t == 0) {
            int fl;
            while (true) {
                asm volatile("ld.acquire.gpu.global.u32 %0, [%1];"
                             : "=r"(fl) : "l"(&g_flag[b]) : "memory");
                if (fl) break;
                __nanosleep(64);
            }
        }
        __syncthreads();
    }

    // ---------------- unified pool phase (proven R7/R9 body) ----------------
    float4 acc = make_float4(0.f, 0.f, 0.f, 0.f);
    {
        const float4 w0 = wb4[l0 / 4 + 0];
        const float4 w1 = wb4[l0 / 4 + 1];
        const float wl[8] = { w0.x, w0.y, w0.z, w0.w, w1.x, w1.y, w1.z, w1.w };
        #pragma unroll
        for (int k = 0; k < 8; ++k) {
            acc.x = fmaf(wl[k], f[k].x, acc.x);
            acc.y = fmaf(wl[k], f[k].y, acc.y);
            acc.z = fmaf(wl[k], f[k].z, acc.z);
            acc.w = fmaf(wl[k], f[k].w, acc.w);
        }
    }

    #pragma unroll
    for (int j = 8; j < LCHUNK_; j += 8) {
        const float4 w0 = wb4[(l0 + j) / 4 + 0];
        const float4 w1 = wb4[(l0 + j) / 4 + 1];
        const float wl[8] = { w0.x, w0.y, w0.z, w0.w, w1.x, w1.y, w1.z, w1.w };
        float4 g[8];
        #pragma unroll
        for (int k = 0; k < 8; ++k)
            g[k] = __ldcs(&fb[(size_t)(l0 + j + k) * NT_ + t]);
        #pragma unroll
        for (int k = 0; k < 8; ++k) {
            acc.x = fmaf(wl[k], g[k].x, acc.x);
            acc.y = fmaf(wl[k], g[k].y, acc.y);
            acc.z = fmaf(wl[k], g[k].z, acc.z);
            acc.w = fmaf(wl[k], g[k].w, acc.w);
        }
    }

    // ---------------- gated epilogue ----------------
    asm volatile("griddepcontrol.wait;" ::: "memory");
    asm volatile("red.global.add.v4.f32 [%0], {%1, %2, %3, %4};"
                 :: "l"(ob), "f"(acc.x), "f"(acc.y), "f"(acc.z), "f"(acc.w)
                 : "memory");
}

// ---------------------------------------------------------------------------
extern "C" void kernel_launch(void* const* d_in, const int* in_sizes, int n_in,
                              void* d_out, int out_size)
{
    const float* feat  = (const float*)d_in[0];   // (B, NL, L, D) f32
    const int*   len32 = (const int*)d_in[1];     // (B,) i32 or i64 (detected)
    const int*   vq32  = (const int*)d_in[2];     // (B, L, 2) i32 or i64 (detected)
    float*       out   = (float*)d_out;           // (B, D) f32

    zero_out_kernel<<<B_, D_>>>(out);

    // Fused kernel with programmatic stream serialization (PDL): starts while
    // the zero kernel runs; only the epilogue reductions are gated.
    cudaLaunchConfig_t cfg = {};
    cfg.gridDim  = dim3(LCHUNKS_, B_);
    cfg.blockDim = dim3(NT_);
    cudaLaunchAttribute attr[1];
    attr[0].id = cudaLaunchAttributeProgrammaticStreamSerialization;
    attr[0].val.programmaticStreamSerializationAllowed = 1;
    cfg.attrs    = attr;
    cfg.numAttrs = 1;
    cudaLaunchKernelEx(&cfg, vq_fused_kernel, feat, len32, vq32, out);
}

// round 13
// speedup vs baseline: 1.4172x; 1.4172x over previous
#include <cuda_runtime.h>

// Problem constants (fixed by the dataset shapes)
#define B_   32
#define NL_  13
#define L_   1024
#define D_   768
#define LCHUNKS_ 32
#define LCHUNK_  (L_ / LCHUNKS_)   // 32 rows per block

// Scratch (no allocation allowed): per-(batch,pos) weights + per-batch lengths.
__device__ float g_w[B_ * L_];
__device__ int   g_len[B_];

// ---------------------------------------------------------------------------
// Kernel 1: per-batch run-length weights + zero the output + publish lengths.
// One block per batch, L_ threads.
// Cheap algorithm (no scan): boundary flags -> block REDUCTION for num_runs,
// then per-thread O(1) LOCAL WALK to the run start/end (adjacent vq pairs
// collide with prob ~1/320^2, so runs are ~always length 1).
// Ends with griddepcontrol.launch_dependents (PDL producer side).
//
// Integer inputs are read through an int32 view with runtime-detected element
// stride (JAX silently downcasts int64->int32 without x64). lengths are in
// [512,1024] (never 0), so word[1]==0  <=>  little-endian int64 layout.
// vq values < 320 < 2^31, so low words fully determine equality either way.
// ---------------------------------------------------------------------------
__global__ void __launch_bounds__(L_, 1)
vq_weights_kernel(const int* __restrict__ len32,
                  const int* __restrict__ vq32,
                  float* __restrict__ out)
{
    const int b    = blockIdx.x;
    const int i    = threadIdx.x;
    const int lane = i & 31;
    const int warp = i >> 5;

    __shared__ int s_bnd[L_];       // boundary flags
    __shared__ int s_v0[L_];        // staged vq low words (component 0)
    __shared__ int s_v1[L_];        // staged vq low words (component 1)
    __shared__ int s_red[32];       // per-warp reduction partials

    // Zero the output slice for this batch (d_out is poisoned to 0xAA).
    if (i < D_) out[b * D_ + i] = 0.0f;

    // dtype detection (uniform)
    const int stride = (len32[1] == 0) ? 2 : 1;

    const int  len   = len32[b * stride];
    const bool valid = i < len;
    if (i == 0) g_len[b] = len;

    const int ebase = (b * L_ + i) * 2;
    int v0 = vq32[(ebase + 0) * stride];
    int v1 = vq32[(ebase + 1) * stride];
    s_v0[i] = v0;
    s_v1[i] = v1;
    __syncthreads();

    // boundary = (i==0 || vq[i]!=vq[i-1]) && valid
    bool bnd;
    if (i == 0) bnd = valid;
    else        bnd = valid && (v0 != s_v0[i - 1] || v1 != s_v1[i - 1]);
    s_bnd[i] = bnd ? 1 : 0;

    // num_runs via block reduction (no scan)
    int r = bnd ? 1 : 0;
    #pragma unroll
    for (int off = 16; off > 0; off >>= 1)
        r += __shfl_down_sync(0xffffffffu, r, off);
    if (lane == 0) s_red[warp] = r;
    __syncthreads();

    int total;
    if (warp == 0) {
        int v = s_red[lane];
        #pragma unroll
        for (int off = 16; off > 0; off >>= 1)
            v += __shfl_xor_sync(0xffffffffu, v, off);
        if (lane == 0) s_red[0] = v;
    }
    __syncthreads();
    total = s_red[0];

    float wv = 0.0f;
    if (valid) {
        // run start: walk down to nearest boundary (expected 0 steps)
        int s = i;
        while (!s_bnd[s]) --s;
        // run end: walk up to next boundary or end of valid region
        int e = i + 1;
        while (e < len && !s_bnd[e]) ++e;
        wv = 1.0f / ((float)total * (float)(e - s));
    }
    g_w[b * L_ + i] = wv;

    // All of this block's global writes are done -> allow dependent launch.
    __syncthreads();
    asm volatile("griddepcontrol.launch_dependents;");
}

// ---------------------------------------------------------------------------
// Kernel 2: weighted pool over the LAST layer of input_feature.
// EXACT R9 body (proven best, 12.768us): grid (32, 32) = 1024 blocks (one
// wave at 8 blocks/SM), 192 threads (one float4 column group per thread).
// Static fully-unrolled 32-row chunk, 8-deep batched __ldcs LDG.128,
// weights as 2x float4 per batch of 8 rows (block-uniform, L1 broadcast).
// PDL: prologue before griddepcontrol.wait. Epilogue: one red.global.v4.f32.
// ---------------------------------------------------------------------------
__global__ void __launch_bounds__(D_ / 4, 8)
vq_pool_kernel(const float* __restrict__ feat, float* __restrict__ out)
{
    const int b  = blockIdx.y;
    const int lc = blockIdx.x;
    const int t  = threadIdx.x;     // 0..191

    const int l0 = lc * LCHUNK_;

    // Prologue independent of kernel 1's results.
    const float4* __restrict__ fb = (const float4*)
        (feat + ((size_t)b * NL_ + (NL_ - 1)) * (size_t)(L_ * D_));
    const float4* __restrict__ wb4 = (const float4*)(g_w + b * L_);
    float* ob = out + b * D_ + t * 4;

    // Wait for the producer kernel's writes (g_len, g_w, zeroed out).
    asm volatile("griddepcontrol.wait;" ::: "memory");

    if (l0 >= g_len[b]) return;     // whole chunk is zero-weight

    float4 acc = make_float4(0.f, 0.f, 0.f, 0.f);

    #pragma unroll
    for (int j = 0; j < LCHUNK_; j += 8) {
        const float4 w0 = wb4[(l0 + j) / 4 + 0];   // weights l0+j .. l0+j+3
        const float4 w1 = wb4[(l0 + j) / 4 + 1];   // weights l0+j+4 .. l0+j+7
        const float wl[8] = { w0.x, w0.y, w0.z, w0.w, w1.x, w1.y, w1.z, w1.w };

        float4 f[8];
        #pragma unroll
        for (int k = 0; k < 8; ++k)
            f[k] = __ldcs(&fb[(size_t)(l0 + j + k) * (D_ / 4) + t]);
        #pragma unroll
        for (int k = 0; k < 8; ++k) {
            acc.x = fmaf(wl[k], f[k].x, acc.x);
            acc.y = fmaf(wl[k], f[k].y, acc.y);
            acc.z = fmaf(wl[k], f[k].z, acc.z);
            acc.w = fmaf(wl[k], f[k].w, acc.w);
        }
    }

    // Single vectorized reduction (16B-aligned)
    asm volatile("red.global.add.v4.f32 [%0], {%1, %2, %3, %4};"
                 :: "l"(ob), "f"(acc.x), "f"(acc.y), "f"(acc.z), "f"(acc.w)
                 : "memory");
}

// ---------------------------------------------------------------------------
extern "C" void kernel_launch(void* const* d_in, const int* in_sizes, int n_in,
                              void* d_out, int out_size)
{
    const float* feat  = (const float*)d_in[0];   // (B, NL, L, D) f32
    const int*   len32 = (const int*)d_in[1];     // (B,) i32 or i64 (detected)
    const int*   vq32  = (const int*)d_in[2];     // (B, L, 2) i32 or i64 (detected)
    float*       out   = (float*)d_out;           // (B, D) f32

    vq_weights_kernel<<<B_, L_>>>(len32, vq32, out);

    // Pool kernel with programmatic stream serialization (PDL).
    cudaLaunchConfig_t cfg = {};
    cfg.gridDim  = dim3(LCHUNKS_, B_);
    cfg.blockDim = dim3(D_ / 4);
    cudaLaunchAttribute attr[1];
    attr[0].id = cudaLaunchAttributeProgrammaticStreamSerialization;
    attr[0].val.programmaticStreamSerializationAllowed = 1;
    cfg.attrs    = attr;
    cfg.numAttrs = 1;
    cudaLaunchKernelEx(&cfg, vq_pool_kernel, feat, out);
}